// round 7
// baseline (speedup 1.0000x reference)
#include <cuda_runtime.h>
#include <cuda_fp16.h>

#define NN 100000
#define H1D 4
#define CD 8
#define NEG 0.2f

// Persistent device scratch (no allocations allowed in kernel_launch).
__device__ float g_ws[H1D];
__device__ float g_wd[H1D];
__device__ float g_acc1[NN * 8];     // per node: S0,T0,S1,T1,S2,T2,S3,T3 (32B aligned)

// Layer-2 per-node accumulator: 64B-aligned record.
//   [0..7]  num[8]   (sector 0: both v4 REDs)
//   [8]     S        (sector 1: scalar RED)
//   [9]     ald      (sector 1: read-only gather during edge2)
//   [10..15] pad
__device__ __align__(64) float g_acc2[NN * 16];

// Packed layer-2 source record: h2 fp16x8 (16B) + als fp32 => 20B in 32B record
struct __align__(32) Node2 {
    __half2 h2[4];
    float   als;
    float   pad[3];
};
__device__ Node2 g_n2[NN];

__device__ __forceinline__ void red4(float* addr, float a, float b, float c, float d) {
    asm volatile("red.global.add.v4.f32 [%0], {%1, %2, %3, %4};"
                 :: "l"(addr), "f"(a), "f"(b), "f"(c), "f"(d) : "memory");
}

// ---------------------------------------------------------------------------
// 1) zero layer-1 accumulators + precompute per-head logit scalars
// ---------------------------------------------------------------------------
__global__ void k_zero_prep(const float* __restrict__ W1,
                            const float* __restrict__ as1,
                            const float* __restrict__ ad1) {
    int t = blockIdx.x * blockDim.x + threadIdx.x;
    int stride = gridDim.x * blockDim.x;
    float4 z = make_float4(0.f, 0.f, 0.f, 0.f);
    float4* a1 = reinterpret_cast<float4*>(g_acc1);  // NN*2 float4
    for (int i = t; i < NN * 2; i += stride) a1[i] = z;
    if (t < H1D) {
        float s = 0.0f, d = 0.0f;
#pragma unroll
        for (int c = 0; c < CD; c++) {
            float w = W1[t * CD + c];
            s += w * as1[t * CD + c];
            d += w * ad1[t * CD + c];
        }
        g_ws[t] = s;
        g_wd[t] = d;
    }
}

// ---------------------------------------------------------------------------
// 2) layer-1 edge pass (real edges only; self-loop folded into k_mid):
//    per head: w = exp(lrelu(x_s*ws + x_d*wd)); acc1[dst] += {S_h: w, T_h: w*x_s}
// ---------------------------------------------------------------------------
__global__ void __launch_bounds__(256) k_edge1(const float* __restrict__ x,
                                               const int* __restrict__ src,
                                               const int* __restrict__ dst,
                                               int E) {
    int t = blockIdx.x * blockDim.x + threadIdx.x;
    if (t >= E) return;
    int s = src[t];
    int d = dst[t];
    float xs = __ldg(&x[s]);
    float xd = __ldg(&x[d]);
    float v[8];
#pragma unroll
    for (int h = 0; h < H1D; h++) {
        float e = xs * g_ws[h] + xd * g_wd[h];
        e = (e > 0.0f) ? e : NEG * e;
        float w = __expf(e);
        v[2 * h]     = w;
        v[2 * h + 1] = w * xs;
    }
    float* base = &g_acc1[(size_t)d * 8];
    red4(base,     v[0], v[1], v[2], v[3]);
    red4(base + 4, v[4], v[5], v[6], v[7]);
}

// ---------------------------------------------------------------------------
// 3) per-node: layer-1 self-loop + epilogue + relu + W2 GEMV + layer-2 logit
//    precompute. Writes packed source record and initializes the full 64B
//    layer-2 accumulator record {num=0, S=0, ald}.
// ---------------------------------------------------------------------------
__global__ void __launch_bounds__(256) k_mid(const float* __restrict__ x,
                                             const float* __restrict__ W1,
                                             const float* __restrict__ b1,
                                             const float* __restrict__ W2,
                                             const float* __restrict__ as2,
                                             const float* __restrict__ ad2) {
    __shared__ float sW2[32 * 8];
    __shared__ float sW1[32];
    __shared__ float sb1[32];
    __shared__ float sa[16];
    int tid = threadIdx.x;
    if (tid < 256) sW2[tid] = W2[tid];
    if (tid < 32) { sW1[tid] = W1[tid]; sb1[tid] = b1[tid]; }
    if (tid < 8)  { sa[tid] = as2[tid]; sa[8 + tid] = ad2[tid]; }
    __syncthreads();

    int n = blockIdx.x * blockDim.x + tid;
    if (n >= NN) return;

    const float4* a1 = reinterpret_cast<const float4*>(&g_acc1[(size_t)n * 8]);
    float4 p0 = a1[0];  // S0,T0,S1,T1
    float4 p1 = a1[1];  // S2,T2,S3,T3

    // layer-1 self-loop contribution (src = dst = n)
    float xd = __ldg(&x[n]);
    float Sv[H1D] = {p0.x, p0.z, p1.x, p1.z};
    float Tv[H1D] = {p0.y, p0.w, p1.y, p1.w};
#pragma unroll
    for (int h = 0; h < H1D; h++) {
        float e = xd * (g_ws[h] + g_wd[h]);
        e = (e > 0.0f) ? e : NEG * e;
        float w = __expf(e);
        Sv[h] += w;
        Tv[h] += w * xd;
    }

    float ts[H1D];
#pragma unroll
    for (int h = 0; h < H1D; h++) ts[h] = Tv[h] / Sv[h];

    float h2[CD];
#pragma unroll
    for (int c = 0; c < CD; c++) h2[c] = 0.0f;
#pragma unroll
    for (int hc = 0; hc < 32; hc++) {
        float r = sW1[hc] * ts[hc >> 3] + sb1[hc];
        r = fmaxf(r, 0.0f);
#pragma unroll
        for (int c = 0; c < CD; c++) h2[c] += r * sW2[hc * 8 + c];
    }
    float als = 0.0f, ald = 0.0f;
#pragma unroll
    for (int c = 0; c < CD; c++) {
        als += h2[c] * sa[c];
        ald += h2[c] * sa[8 + c];
    }

    // pack h2 -> fp16x8 (one 16B store) + als
    __half2 pk[4];
    pk[0] = __floats2half2_rn(h2[0], h2[1]);
    pk[1] = __floats2half2_rn(h2[2], h2[3]);
    pk[2] = __floats2half2_rn(h2[4], h2[5]);
    pk[3] = __floats2half2_rn(h2[6], h2[7]);
    *reinterpret_cast<uint4*>(g_n2[n].h2) = *reinterpret_cast<const uint4*>(pk);
    g_n2[n].als = als;

    // init layer-2 accumulator record: num=0 (32B), {S=0, ald} (8B)
    float* rec = &g_acc2[(size_t)n * 16];
    float4 z = make_float4(0.f, 0.f, 0.f, 0.f);
    reinterpret_cast<float4*>(rec)[0] = z;
    reinterpret_cast<float4*>(rec)[1] = z;
    *reinterpret_cast<float2*>(rec + 8) = make_float2(0.0f, ald);
}

// ---------------------------------------------------------------------------
// 4) layer-2 edge pass (real edges only): w = exp(lrelu(als[s] + ald[d]));
//    rec[d].num += w*h2[s] (2 v4-REDs, one sector); rec[d].S += w (2nd sector)
// ---------------------------------------------------------------------------
__global__ void __launch_bounds__(256) k_edge2(const int* __restrict__ src,
                                               const int* __restrict__ dst,
                                               int E) {
    int t = blockIdx.x * blockDim.x + threadIdx.x;
    if (t >= E) return;
    int s = src[t];
    int d = dst[t];

    uint4 raw = *reinterpret_cast<const uint4*>(g_n2[s].h2);
    __half2 pk[4];
    *reinterpret_cast<uint4*>(pk) = raw;
    float als = g_n2[s].als;

    float* rec = &g_acc2[(size_t)d * 16];
    float ald = __ldg(rec + 9);

    float e = als + ald;
    e = (e > 0.0f) ? e : NEG * e;
    float w = __expf(e);

    float2 f0 = __half22float2(pk[0]);
    float2 f1 = __half22float2(pk[1]);
    float2 f2 = __half22float2(pk[2]);
    float2 f3 = __half22float2(pk[3]);

    red4(rec,     w * f0.x, w * f0.y, w * f1.x, w * f1.y);
    red4(rec + 4, w * f2.x, w * f2.y, w * f3.x, w * f3.y);
    atomicAdd(rec + 8, w);
}

// ---------------------------------------------------------------------------
// 5) final: add layer-2 self-loop analytically, normalize + bias -> out
// ---------------------------------------------------------------------------
__global__ void __launch_bounds__(256) k_final(float* __restrict__ out,
                                               const float* __restrict__ b2) {
    __shared__ float sb2[8];
    int tid = threadIdx.x;
    if (tid < 8) sb2[tid] = b2[tid];
    __syncthreads();

    int n = blockIdx.x * blockDim.x + tid;
    if (n >= NN) return;

    const float* rec = &g_acc2[(size_t)n * 16];
    float4 n0 = reinterpret_cast<const float4*>(rec)[0];
    float4 n1 = reinterpret_cast<const float4*>(rec)[1];
    float S   = rec[8];
    float ald = rec[9];

    uint4 raw = *reinterpret_cast<const uint4*>(g_n2[n].h2);
    __half2 pk[4];
    *reinterpret_cast<uint4*>(pk) = raw;
    float als = g_n2[n].als;

    float e = als + ald;
    e = (e > 0.0f) ? e : NEG * e;
    float w = __expf(e);

    float2 f0 = __half22float2(pk[0]);
    float2 f1 = __half22float2(pk[1]);
    float2 f2 = __half22float2(pk[2]);
    float2 f3 = __half22float2(pk[3]);

    float inv = 1.0f / (S + w);
    float4 o0 = make_float4((n0.x + w * f0.x) * inv + sb2[0],
                            (n0.y + w * f0.y) * inv + sb2[1],
                            (n0.z + w * f1.x) * inv + sb2[2],
                            (n0.w + w * f1.y) * inv + sb2[3]);
    float4 o1 = make_float4((n1.x + w * f2.x) * inv + sb2[4],
                            (n1.y + w * f2.y) * inv + sb2[5],
                            (n1.z + w * f3.x) * inv + sb2[6],
                            (n1.w + w * f3.y) * inv + sb2[7]);
    float4* ob = reinterpret_cast<float4*>(&out[(size_t)n * 8]);
    ob[0] = o0;
    ob[1] = o1;
}

extern "C" void kernel_launch(void* const* d_in, const int* in_sizes, int n_in,
                              void* d_out, int out_size) {
    const float* x   = (const float*)d_in[0];
    const int*   ei  = (const int*)d_in[1];
    const float* W1  = (const float*)d_in[2];
    const float* as1 = (const float*)d_in[3];
    const float* ad1 = (const float*)d_in[4];
    const float* b1  = (const float*)d_in[5];
    const float* W2  = (const float*)d_in[6];
    const float* as2 = (const float*)d_in[7];
    const float* ad2 = (const float*)d_in[8];
    const float* b2  = (const float*)d_in[9];
    float* out = (float*)d_out;

    int E = in_sizes[1] / 2;
    const int* src = ei;
    const int* dst = ei + E;

    int tb = 256;
    int eb = (E + tb - 1) / tb;
    int nb = (NN + tb - 1) / tb;

    k_zero_prep<<<1024, tb>>>(W1, as1, ad1);
    k_edge1<<<eb, tb>>>(x, src, dst, E);
    k_mid<<<nb, tb>>>(x, W1, b1, W2, as2, ad2);
    k_edge2<<<eb, tb>>>(src, dst, E);
    k_final<<<nb, tb>>>(out, b2);
}

// round 11
// speedup vs baseline: 1.0858x; 1.0858x over previous
#include <cuda_runtime.h>
#include <cuda_fp16.h>

#define NN 100000
#define H1D 4
#define CD 8
#define NEG 0.2f

// Persistent device scratch (no allocations allowed in kernel_launch).
__device__ float g_ws[H1D];
__device__ float g_wd[H1D];
__device__ float g_acc1[NN * 8];    // per node: S0,T0,S1,T1,S2,T2,S3,T3 (32B aligned)
__device__ float g_acc2[NN * 12];   // per node: S, num[0..7], pad x3 (48B stride, R4 layout)

// Packed layer-2 source record: h2 fp16x8 (16B) + als fp32 => 20B in 32B record
struct __align__(32) Node2 {
    __half2 h2[4];
    float   als;
    float   pad[3];
};
__device__ Node2 g_n2[NN];
__device__ float g_ald[NN];         // dense read-only during edge2 (L1-cacheable)

__device__ __forceinline__ void red4(float* addr, float a, float b, float c, float d) {
    asm volatile("red.global.add.v4.f32 [%0], {%1, %2, %3, %4};"
                 :: "l"(addr), "f"(a), "f"(b), "f"(c), "f"(d) : "memory");
}

// ---------------------------------------------------------------------------
// 1) zero accumulators + precompute per-head logit scalars
// ---------------------------------------------------------------------------
__global__ void k_zero_prep(const float* __restrict__ W1,
                            const float* __restrict__ as1,
                            const float* __restrict__ ad1) {
    int t = blockIdx.x * blockDim.x + threadIdx.x;
    int stride = gridDim.x * blockDim.x;
    float4 z = make_float4(0.f, 0.f, 0.f, 0.f);
    float4* a1 = reinterpret_cast<float4*>(g_acc1);   // NN*2 float4
    float4* a2 = reinterpret_cast<float4*>(g_acc2);   // NN*3 float4
    for (int i = t; i < NN * 3; i += stride) {
        a2[i] = z;
        if (i < NN * 2) a1[i] = z;
    }
    if (t < H1D) {
        float s = 0.0f, d = 0.0f;
#pragma unroll
        for (int c = 0; c < CD; c++) {
            float w = W1[t * CD + c];
            s += w * as1[t * CD + c];
            d += w * ad1[t * CD + c];
        }
        g_ws[t] = s;
        g_wd[t] = d;
    }
}

// ---------------------------------------------------------------------------
// 2) layer-1 edge pass (real edges only), 2 edges per thread:
//    per head: w = exp(lrelu(x_s*ws + x_d*wd)); acc1[dst] += {S_h: w, T_h: w*x_s}
// ---------------------------------------------------------------------------
__device__ __forceinline__ void edge1_body(const float* __restrict__ x, int s, int d) {
    float xs = __ldg(&x[s]);
    float xd = __ldg(&x[d]);
    float v[8];
#pragma unroll
    for (int h = 0; h < H1D; h++) {
        float e = xs * g_ws[h] + xd * g_wd[h];
        e = (e > 0.0f) ? e : NEG * e;
        float w = __expf(e);
        v[2 * h]     = w;
        v[2 * h + 1] = w * xs;
    }
    float* base = &g_acc1[(size_t)d * 8];
    red4(base,     v[0], v[1], v[2], v[3]);
    red4(base + 4, v[4], v[5], v[6], v[7]);
}

__global__ void __launch_bounds__(256) k_edge1(const float* __restrict__ x,
                                               const int* __restrict__ src,
                                               const int* __restrict__ dst,
                                               int E) {
    int t = blockIdx.x * blockDim.x + threadIdx.x;
    int i0 = 2 * t;
    if (i0 >= E) return;
    if (i0 + 1 < E) {
        int2 ss = *reinterpret_cast<const int2*>(src + i0);
        int2 dd = *reinterpret_cast<const int2*>(dst + i0);
        edge1_body(x, ss.x, dd.x);
        edge1_body(x, ss.y, dd.y);
    } else {
        edge1_body(x, src[i0], dst[i0]);
    }
}

// ---------------------------------------------------------------------------
// 3) per-node: layer-1 self-loop + epilogue + relu + W2 GEMV + layer-2 logit
//    precompute. Writes packed source record + dense ald.
// ---------------------------------------------------------------------------
__global__ void __launch_bounds__(256) k_mid(const float* __restrict__ x,
                                             const float* __restrict__ W1,
                                             const float* __restrict__ b1,
                                             const float* __restrict__ W2,
                                             const float* __restrict__ as2,
                                             const float* __restrict__ ad2) {
    __shared__ float sW2[32 * 8];
    __shared__ float sW1[32];
    __shared__ float sb1[32];
    __shared__ float sa[16];
    int tid = threadIdx.x;
    if (tid < 256) sW2[tid] = W2[tid];
    if (tid < 32) { sW1[tid] = W1[tid]; sb1[tid] = b1[tid]; }
    if (tid < 8)  { sa[tid] = as2[tid]; sa[8 + tid] = ad2[tid]; }
    __syncthreads();

    int n = blockIdx.x * blockDim.x + tid;
    if (n >= NN) return;

    const float4* a1 = reinterpret_cast<const float4*>(&g_acc1[(size_t)n * 8]);
    float4 p0 = a1[0];  // S0,T0,S1,T1
    float4 p1 = a1[1];  // S2,T2,S3,T3

    // layer-1 self-loop contribution (src = dst = n)
    float xd = __ldg(&x[n]);
    float Sv[H1D] = {p0.x, p0.z, p1.x, p1.z};
    float Tv[H1D] = {p0.y, p0.w, p1.y, p1.w};
#pragma unroll
    for (int h = 0; h < H1D; h++) {
        float e = xd * (g_ws[h] + g_wd[h]);
        e = (e > 0.0f) ? e : NEG * e;
        float w = __expf(e);
        Sv[h] += w;
        Tv[h] += w * xd;
    }

    float ts[H1D];
#pragma unroll
    for (int h = 0; h < H1D; h++) ts[h] = Tv[h] / Sv[h];

    float h2[CD];
#pragma unroll
    for (int c = 0; c < CD; c++) h2[c] = 0.0f;
#pragma unroll
    for (int hc = 0; hc < 32; hc++) {
        float r = sW1[hc] * ts[hc >> 3] + sb1[hc];
        r = fmaxf(r, 0.0f);
#pragma unroll
        for (int c = 0; c < CD; c++) h2[c] += r * sW2[hc * 8 + c];
    }
    float als = 0.0f, ald = 0.0f;
#pragma unroll
    for (int c = 0; c < CD; c++) {
        als += h2[c] * sa[c];
        ald += h2[c] * sa[8 + c];
    }

    // pack h2 -> fp16x8 (one 16B store) + als
    __half2 pk[4];
    pk[0] = __floats2half2_rn(h2[0], h2[1]);
    pk[1] = __floats2half2_rn(h2[2], h2[3]);
    pk[2] = __floats2half2_rn(h2[4], h2[5]);
    pk[3] = __floats2half2_rn(h2[6], h2[7]);
    *reinterpret_cast<uint4*>(g_n2[n].h2) = *reinterpret_cast<const uint4*>(pk);
    g_n2[n].als = als;
    g_ald[n] = ald;
}

// ---------------------------------------------------------------------------
// 4) layer-2 edge pass (real edges only), 2 edges per thread:
//    w = exp(lrelu(als[s] + ald[d])); acc2[d] += {S: w, num[c]: w*h2[s][c]}
//    (R4 record layout: S,n0..n6 via two v4 REDs; n7 via scalar RED)
// ---------------------------------------------------------------------------
__device__ __forceinline__ void edge2_body(int s, int d) {
    uint4 raw = *reinterpret_cast<const uint4*>(g_n2[s].h2);
    __half2 pk[4];
    *reinterpret_cast<uint4*>(pk) = raw;
    float als = g_n2[s].als;
    float ald = __ldg(&g_ald[d]);

    float e = als + ald;
    e = (e > 0.0f) ? e : NEG * e;
    float w = __expf(e);

    float2 f0 = __half22float2(pk[0]);
    float2 f1 = __half22float2(pk[1]);
    float2 f2 = __half22float2(pk[2]);
    float2 f3 = __half22float2(pk[3]);

    float* ab = &g_acc2[(size_t)d * 12];
    red4(ab,     w,        w * f0.x, w * f0.y, w * f1.x);
    red4(ab + 4, w * f1.y, w * f2.x, w * f2.y, w * f3.x);
    atomicAdd(ab + 8, w * f3.y);
}

__global__ void __launch_bounds__(256) k_edge2(const int* __restrict__ src,
                                               const int* __restrict__ dst,
                                               int E) {
    int t = blockIdx.x * blockDim.x + threadIdx.x;
    int i0 = 2 * t;
    if (i0 >= E) return;
    if (i0 + 1 < E) {
        int2 ss = *reinterpret_cast<const int2*>(src + i0);
        int2 dd = *reinterpret_cast<const int2*>(dst + i0);
        edge2_body(ss.x, dd.x);
        edge2_body(ss.y, dd.y);
    } else {
        edge2_body(src[i0], dst[i0]);
    }
}

// ---------------------------------------------------------------------------
// 5) final: add layer-2 self-loop analytically, normalize + bias -> out
// ---------------------------------------------------------------------------
__global__ void __launch_bounds__(256) k_final(float* __restrict__ out,
                                               const float* __restrict__ b2) {
    __shared__ float sb2[8];
    int tid = threadIdx.x;
    if (tid < 8) sb2[tid] = b2[tid];
    __syncthreads();

    int n = blockIdx.x * blockDim.x + tid;
    if (n >= NN) return;

    const float* ab = &g_acc2[(size_t)n * 12];
    float S  = ab[0];
    float4 q0 = make_float4(ab[1], ab[2], ab[3], ab[4]);
    float4 q1 = make_float4(ab[5], ab[6], ab[7], ab[8]);

    // layer-2 self-loop from own record
    uint4 raw = *reinterpret_cast<const uint4*>(g_n2[n].h2);
    __half2 pk[4];
    *reinterpret_cast<uint4*>(pk) = raw;
    float als = g_n2[n].als;
    float ald = g_ald[n];

    float e = als + ald;
    e = (e > 0.0f) ? e : NEG * e;
    float w = __expf(e);

    float2 f0 = __half22float2(pk[0]);
    float2 f1 = __half22float2(pk[1]);
    float2 f2 = __half22float2(pk[2]);
    float2 f3 = __half22float2(pk[3]);

    float inv = 1.0f / (S + w);
    float4 o0 = make_float4((q0.x + w * f0.x) * inv + sb2[0],
                            (q0.y + w * f0.y) * inv + sb2[1],
                            (q0.z + w * f1.x) * inv + sb2[2],
                            (q0.w + w * f1.y) * inv + sb2[3]);
    float4 o1 = make_float4((q1.x + w * f2.x) * inv + sb2[4],
                            (q1.y + w * f2.y) * inv + sb2[5],
                            (q1.z + w * f3.x) * inv + sb2[6],
                            (q1.w + w * f3.y) * inv + sb2[7]);
    float4* ob = reinterpret_cast<float4*>(&out[(size_t)n * 8]);
    ob[0] = o0;
    ob[1] = o1;
}

extern "C" void kernel_launch(void* const* d_in, const int* in_sizes, int n_in,
                              void* d_out, int out_size) {
    const float* x   = (const float*)d_in[0];
    const int*   ei  = (const int*)d_in[1];
    const float* W1  = (const float*)d_in[2];
    const float* as1 = (const float*)d_in[3];
    const float* ad1 = (const float*)d_in[4];
    const float* b1  = (const float*)d_in[5];
    const float* W2  = (const float*)d_in[6];
    const float* as2 = (const float*)d_in[7];
    const float* ad2 = (const float*)d_in[8];
    const float* b2  = (const float*)d_in[9];
    float* out = (float*)d_out;

    int E = in_sizes[1] / 2;
    const int* src = ei;
    const int* dst = ei + E;

    int tb = 256;
    int eb2 = ((E + 1) / 2 + tb - 1) / tb;   // 2 edges per thread
    int nb = (NN + tb - 1) / tb;

    k_zero_prep<<<1024, tb>>>(W1, as1, ad1);
    k_edge1<<<eb2, tb>>>(x, src, dst, E);
    k_mid<<<nb, tb>>>(x, W1, b1, W2, as2, ad2);
    k_edge2<<<eb2, tb>>>(src, dst, E);
    k_final<<<nb, tb>>>(out, b2);
}